// round 16
// baseline (speedup 1.0000x reference)
#include <cuda_runtime.h>
#include <math.h>
#include <stdint.h>

// Problem shapes (fixed by dataset)
#define SS 2048
#define BB 32
#define HH 1024

// u GEMM tiling (proven R11/R12 config)
#define NOB 64
#define OC  16

#define GRID 148        // persistent co-resident blocks
#define NST  3          // smem ring stages
#define CHUNK 65536     // 64 KB = 16 batches x 4 KB (half a slab)

#define SM_MBAR  (NST * CHUNK)          // 3 full-barriers at +st*8
#define SM_TOTAL (SM_MBAR + NST * 8)

// Scratch (static __device__ — no allocations allowed)
__device__ float g_u_part[NOB][BB * HH];  // 8 MB (L2-resident)
__device__ float g_u[BB * HH];            // 128 KB
__device__ float g_scores[BB * SS];       // 256 KB
__device__ unsigned g_bar;                // grid-barrier counter

// ---------------------------------------------------------------------------
// PTX helpers
// ---------------------------------------------------------------------------
__device__ __forceinline__ uint32_t smem_u32(const void* p) {
    uint32_t a;
    asm("{ .reg .u64 t; cvta.to.shared.u64 t, %1; cvt.u32.u64 %0, t; }"
        : "=r"(a) : "l"(p));
    return a;
}
__device__ __forceinline__ void mbar_init(uint32_t mbar, uint32_t count) {
    asm volatile("mbarrier.init.shared.b64 [%0], %1;" :: "r"(mbar), "r"(count)
                 : "memory");
}
__device__ __forceinline__ void mbar_expect_tx(uint32_t mbar, uint32_t bytes) {
    asm volatile("mbarrier.arrive.expect_tx.shared.b64 _, [%0], %1;"
                 :: "r"(mbar), "r"(bytes) : "memory");
}
__device__ __forceinline__ void mbar_wait(uint32_t mbar, uint32_t parity) {
    asm volatile(
        "{\n\t"
        ".reg .pred P;\n\t"
        "WAIT_%=:\n\t"
        "mbarrier.try_wait.parity.acquire.cta.shared::cta.b64 P, [%0], %1, 0x989680;\n\t"
        "@P bra.uni DONE_%=;\n\t"
        "bra.uni WAIT_%=;\n\t"
        "DONE_%=:\n\t"
        "}" :: "r"(mbar), "r"(parity) : "memory");
}
__device__ __forceinline__ void bulk_g2s(uint32_t dst, const void* src,
                                         uint32_t bytes, uint32_t mbar) {
    asm volatile(
        "cp.async.bulk.shared::cluster.global.mbarrier::complete_tx::bytes "
        "[%0], [%1], %2, [%3];"
        :: "r"(dst), "l"(src), "r"(bytes), "r"(mbar) : "memory");
}

// ---------------------------------------------------------------------------
// K_A: u_part (proven R11/R12 body). grid (4, NOB, 2) = 512 x 256.
// ---------------------------------------------------------------------------
__global__ void k_upart(const float* __restrict__ hidden,
                        const float* __restrict__ W) {
    __shared__ float hs[OC * 16];
    const int t = threadIdx.x;
    const int h = blockIdx.x * 256 + t;
    const int o0 = blockIdx.y * OC;
    const int bbase = blockIdx.z * 16;

    if (t < OC * 16) {
        int o = t >> 4, bl = t & 15;
        hs[t] = hidden[(bbase + bl) * HH + o0 + o];
    }
    __syncthreads();

    float w[OC];
#pragma unroll
    for (int o = 0; o < OC; ++o)
        w[o] = W[(size_t)(o0 + o) * HH + h];

    float acc[16];
#pragma unroll
    for (int bl = 0; bl < 16; ++bl) acc[bl] = 0.f;

    const float4* hs4 = reinterpret_cast<const float4*>(hs);
#pragma unroll
    for (int o = 0; o < OC; ++o) {
#pragma unroll
        for (int q = 0; q < 4; ++q) {
            float4 hv = hs4[o * 4 + q];
            acc[q * 4 + 0] = fmaf(hv.x, w[o], acc[q * 4 + 0]);
            acc[q * 4 + 1] = fmaf(hv.y, w[o], acc[q * 4 + 1]);
            acc[q * 4 + 2] = fmaf(hv.z, w[o], acc[q * 4 + 2]);
            acc[q * 4 + 3] = fmaf(hv.w, w[o], acc[q * 4 + 3]);
        }
    }

#pragma unroll
    for (int bl = 0; bl < 16; ++bl)
        g_u_part[blockIdx.y][(bbase + bl) * HH + h] = acc[bl];
}

// ---------------------------------------------------------------------------
// K_B: reduce 64 partials (8 MB, L2-hot). grid 256 x 256.
// ---------------------------------------------------------------------------
__global__ void __launch_bounds__(256) k_ureduce() {
    __shared__ float tmp[256];
    const int t = threadIdx.x;
    const int j = blockIdx.x * 128 + (t & 127);
    const int g = t >> 7;

    float s = 0.f;
#pragma unroll 8
    for (int p = g * 32; p < g * 32 + 32; ++p) s += g_u_part[p][j];
    tmp[t] = s;
    __syncthreads();
    if (t < 128) g_u[j] = tmp[t] + tmp[t + 128];
}

// ---------------------------------------------------------------------------
// K_C: scores via bulk-async smem ring (deadlock-proof skeleton) + softmax.
// Chunks q = 0..2*cnt-1: chunk q = batches (q&1)*16..+15 of slab
// s = blk + (q>>1)*GRID (64 KB contiguous). Stage q%3.
//   iteration q: t0 issues fill for chunk q+2 (stage recycled: its last
//   consumers finished before the __syncthreads of iteration q-1, which t0
//   has passed); ALL threads wait full[q%3] parity (q/3)&1; the 16 warps of
//   half q&1 dot their 4 KB row vs register u; __syncthreads recycles.
// Fills per stage are serialized by the per-iteration sync => parity can
// never run ahead. No empty barriers, no producer/consumer interleave.
// ---------------------------------------------------------------------------
__global__ void __launch_bounds__(1024, 1)
k_scores_softmax(const float* __restrict__ enc, float* __restrict__ out) {
    extern __shared__ char smem[];
    __shared__ float red[32];
    const int t = threadIdx.x;
    const int warp = t >> 5;
    const int lane = t & 31;
    const int b = warp;
    const int half = warp >> 4;
    const int blk = blockIdx.x;

    const uint32_t sbase = smem_u32(smem);
    const int cnt = (blk < 124) ? 14 : 13;   // 124*14 + 24*13 = 2048
    const int NC = 2 * cnt;

    if (t == 0) {
#pragma unroll
        for (int st = 0; st < NST; ++st)
            mbar_init(sbase + SM_MBAR + st * 8, 1);
    }
    __syncthreads();

    // u[b] -> registers, once
    const float4* ub = reinterpret_cast<const float4*>(g_u + b * HH);
    float4 u[8];
#pragma unroll
    for (int c = 0; c < 8; ++c) u[c] = ub[c * 32 + lane];

    // prefill chunks 0,1 (stages 0,1; never used before)
    if (t == 0) {
#pragma unroll
        for (int q = 0; q < 2; ++q) {
            const int s = blk + (q >> 1) * GRID;
            const char* src =
                (const char*)(enc + ((size_t)s * BB + (q & 1) * 16) * HH);
            mbar_expect_tx(sbase + SM_MBAR + (q % NST) * 8, CHUNK);
            bulk_g2s(sbase + (q % NST) * CHUNK, src, CHUNK,
                     sbase + SM_MBAR + (q % NST) * 8);
        }
    }

    for (int q = 0; q < NC; ++q) {
        // stay 2 chunks ahead
        if (t == 0 && q + 2 < NC) {
            const int j = q + 2;
            const int s = blk + (j >> 1) * GRID;
            const char* src =
                (const char*)(enc + ((size_t)s * BB + (j & 1) * 16) * HH);
            mbar_expect_tx(sbase + SM_MBAR + (j % NST) * 8, CHUNK);
            bulk_g2s(sbase + (j % NST) * CHUNK, src, CHUNK,
                     sbase + SM_MBAR + (j % NST) * 8);
        }

        mbar_wait(sbase + SM_MBAR + (q % NST) * 8, (q / NST) & 1);

        if ((q & 1) == half) {   // warp-uniform branch
            const float4* row = reinterpret_cast<const float4*>(
                smem + (q % NST) * CHUNK + (warp & 15) * 4096);
            float a = 0.f;
#pragma unroll
            for (int c = 0; c < 8; ++c) {
                float4 e = row[c * 32 + lane];
                a += e.x * u[c].x + e.y * u[c].y + e.z * u[c].z + e.w * u[c].w;
            }
#pragma unroll
            for (int off = 16; off; off >>= 1)
                a += __shfl_xor_sync(0xFFFFFFFFu, a, off);
            if (lane == 0) g_scores[b * SS + blk + (q >> 1) * GRID] = a;
        }
        __syncthreads();   // recycle stage q%3
    }

    // ---- ONE grid barrier among 148 blocks (R14-proven) ----
    if (t == 0) {
        __threadfence();                       // release scores
        atomicAdd(&g_bar, 1u);
        while (atomicAdd(&g_bar, 0u) < GRID) __nanosleep(32);
        __threadfence();                       // acquire
    }
    __syncthreads();

    // ---- softmax (blocks 0..31, batch bb = blk) ----
    if (blk < BB) {
        const int bb = blk;
        float v0 = g_scores[bb * SS + t];
        float v1 = g_scores[bb * SS + t + 1024];

        float m = fmaxf(v0, v1);
#pragma unroll
        for (int off = 16; off; off >>= 1)
            m = fmaxf(m, __shfl_xor_sync(0xFFFFFFFFu, m, off));
        if (lane == 0) red[warp] = m;
        __syncthreads();
        if (warp == 0) {
            float x = red[lane];
#pragma unroll
            for (int off = 16; off; off >>= 1)
                x = fmaxf(x, __shfl_xor_sync(0xFFFFFFFFu, x, off));
            if (lane == 0) red[0] = x;
        }
        __syncthreads();
        const float bm = red[0];
        __syncthreads();  // before reusing red[]

        v0 = __expf(v0 - bm);
        v1 = __expf(v1 - bm);
        float s = v0 + v1;
#pragma unroll
        for (int off = 16; off; off >>= 1)
            s += __shfl_xor_sync(0xFFFFFFFFu, s, off);
        if (lane == 0) red[warp] = s;
        __syncthreads();
        if (warp == 0) {
            float x = red[lane];
#pragma unroll
            for (int off = 16; off; off >>= 1)
                x += __shfl_xor_sync(0xFFFFFFFFu, x, off);
            if (lane == 0) red[0] = x;
        }
        __syncthreads();
        const float inv = 1.f / red[0];

        out[bb * SS + t]        = v0 * inv;
        out[bb * SS + t + 1024] = v1 * inv;
    }
}

// ---------------------------------------------------------------------------
// Inputs (metadata order): hidden [B,H], encoder_outputs [S,B,H], W [H,H], b [H]
// Bias is irrelevant (softmax shift invariance).
// ---------------------------------------------------------------------------
extern "C" void kernel_launch(void* const* d_in, const int* in_sizes, int n_in,
                              void* d_out, int out_size) {
    const float* hidden = (const float*)d_in[0];
    const float* enc    = (const float*)d_in[1];
    const float* W      = (const float*)d_in[2];
    float* out          = (float*)d_out;

    cudaFuncSetAttribute(k_scores_softmax,
                         cudaFuncAttributeMaxDynamicSharedMemorySize, SM_TOTAL);

    // Zero the barrier counter each invocation (captured as a graph node).
    void* bar_ptr;
    cudaGetSymbolAddress(&bar_ptr, g_bar);
    cudaMemsetAsync(bar_ptr, 0, sizeof(unsigned));

    k_upart<<<dim3(HH / 256, NOB, 2), 256>>>(hidden, W);
    k_ureduce<<<256, 256>>>();
    k_scores_softmax<<<GRID, 1024, SM_TOTAL>>>(enc, out);
}